// round 1
// baseline (speedup 1.0000x reference)
#include <cuda_runtime.h>
#include <math.h>

#define Bb 2
#define Ll 2048
#define Dd 1024
#define Hh 16
#define HDIM 64
#define NT (Bb*Ll)          // 4096 tokens
#define ATT_SCALE 0.125f    // 1/sqrt(64)

// Scratch (device globals — allocation-free per harness rules)
__device__ float g_qkv[(size_t)NT * 3 * Dd];   // [token][3*D]
__device__ float g_q[(size_t)NT * Dd];         // [b][h][l][hd]
__device__ float g_k[(size_t)NT * Dd];         // [b][h][l][hd]
__device__ float g_v[(size_t)NT * Dd];         // [b][h][l][hd]
__device__ float g_ao[(size_t)NT * Dd];        // [token][h*64+hd]

// ---------------------------------------------------------------------------
// Tiled SGEMM: C[M,N] = A[M,K] @ B[K,N], all row-major fp32.
// BM=BN=128, BK=16, 256 threads, 8x8 per thread. M,N,K multiples of 128/16.
// ---------------------------------------------------------------------------
__global__ void __launch_bounds__(256) sgemm128(const float* __restrict__ A,
                                                const float* __restrict__ B,
                                                float* __restrict__ C,
                                                int M, int N, int K)
{
    __shared__ float As[16][132];   // transposed: As[k][m]
    __shared__ float Bs[16][132];   // Bs[k][n]

    const int tid = threadIdx.x;
    const int tx = tid & 15, ty = tid >> 4;
    const int brow = blockIdx.y * 128;
    const int bcol = blockIdx.x * 128;

    float acc[8][8];
#pragma unroll
    for (int i = 0; i < 8; i++)
#pragma unroll
        for (int j = 0; j < 8; j++) acc[i][j] = 0.f;

    for (int k0 = 0; k0 < K; k0 += 16) {
#pragma unroll
        for (int u = 0; u < 2; u++) {
            int idx = tid + u * 256;            // 0..511
            int r = idx >> 2;                   // 0..127
            int c4 = (idx & 3) * 4;             // 0,4,8,12
            float4 v = *(const float4*)&A[(size_t)(brow + r) * K + k0 + c4];
            As[c4 + 0][r] = v.x;
            As[c4 + 1][r] = v.y;
            As[c4 + 2][r] = v.z;
            As[c4 + 3][r] = v.w;
        }
#pragma unroll
        for (int u = 0; u < 2; u++) {
            int idx = tid + u * 256;
            int r = idx >> 5;                   // 0..15
            int c = (idx & 31) * 4;             // 0..124
            *(float4*)&Bs[r][c] = *(const float4*)&B[(size_t)(k0 + r) * N + bcol + c];
        }
        __syncthreads();

#pragma unroll
        for (int kk = 0; kk < 16; kk++) {
            float a[8], bv[8];
            *(float4*)&a[0]  = *(float4*)&As[kk][ty * 8];
            *(float4*)&a[4]  = *(float4*)&As[kk][ty * 8 + 4];
            *(float4*)&bv[0] = *(float4*)&Bs[kk][tx * 8];
            *(float4*)&bv[4] = *(float4*)&Bs[kk][tx * 8 + 4];
#pragma unroll
            for (int i = 0; i < 8; i++)
#pragma unroll
                for (int j = 0; j < 8; j++)
                    acc[i][j] = fmaf(a[i], bv[j], acc[i][j]);
        }
        __syncthreads();
    }

#pragma unroll
    for (int i = 0; i < 8; i++) {
        float4* cp = (float4*)&C[(size_t)(brow + ty * 8 + i) * N + bcol + tx * 8];
        cp[0] = make_float4(acc[i][0], acc[i][1], acc[i][2], acc[i][3]);
        cp[1] = make_float4(acc[i][4], acc[i][5], acc[i][6], acc[i][7]);
    }
}

// ---------------------------------------------------------------------------
// RoPE + transpose to head-major [b][h][l][hd] for q,k (roped) and v (copy).
// One thread per (token, head, pair-index i<32).
// ---------------------------------------------------------------------------
__global__ void __launch_bounds__(256) rope_kernel(const float* __restrict__ cosb,
                                                   const float* __restrict__ sinb)
{
    int idx = blockIdx.x * blockDim.x + threadIdx.x;   // < NT*Hh*32
    int i = idx & 31;
    int h = (idx >> 5) & 15;
    int t = idx >> 9;                                  // token 0..4095
    int b = t >> 11;                                   // /Ll
    int l = t & (Ll - 1);

    float c = cosb[(size_t)t * (Dd / 2) + h * 32 + i];
    float s = sinb[(size_t)t * (Dd / 2) + h * 32 + i];

    const float* row = &g_qkv[(size_t)t * 3 * Dd];
    float q1 = row[h * 64 + i],            q2 = row[h * 64 + 32 + i];
    float k1 = row[Dd + h * 64 + i],       k2 = row[Dd + h * 64 + 32 + i];
    float v1 = row[2 * Dd + h * 64 + i],   v2 = row[2 * Dd + h * 64 + 32 + i];

    size_t o = ((size_t)(b * Hh + h) * Ll + l) * 64;
    g_q[o + i]      = q1 * c - q2 * s;
    g_q[o + 32 + i] = q1 * s + q2 * c;
    g_k[o + i]      = k1 * c - k2 * s;
    g_k[o + 32 + i] = k1 * s + k2 * c;
    g_v[o + i]      = v1;
    g_v[o + 32 + i] = v2;
}

// ---------------------------------------------------------------------------
// Flash attention fp32: 64 q-rows per block, online softmax over 32 kv-tiles.
// 256 threads (16x16), each owns a 4x4 micro-tile of S/P and of O.
// Dyn smem: Qt[64][68](d-major) Kt[64][68](d-major) Vs[64][68] Pt[64][68](k-major)
// ---------------------------------------------------------------------------
__global__ void __launch_bounds__(256) flash_kernel(const int* __restrict__ mask)
{
    extern __shared__ float fsh[];
    float* Qt = fsh;                 // Qt[d*68 + q]
    float* Kt = Qt + 64 * 68;        // Kt[d*68 + k]
    float* Vs = Kt + 64 * 68;        // Vs[k*68 + d]
    float* Pt = Vs + 64 * 68;        // Pt[k*68 + q]
    __shared__ float mk[64];

    const int qt = blockIdx.x, h = blockIdx.y, b = blockIdx.z;
    const int tid = threadIdx.x;
    const int tx = tid & 15, ty = tid >> 4;

    const size_t head_off = (size_t)(b * Hh + h) * Ll * 64;
    const float* Qg = g_q + head_off;
    const float* Kg = g_k + head_off;
    const float* Vg = g_v + head_off;

    // Load Q tile transposed into smem (visible after first barrier in loop)
    {
        int r = tid >> 2, f = tid & 3;
#pragma unroll
        for (int j = 0; j < 4; j++) {
            int d0 = (f + j * 4) * 4;
            float4 v = *(const float4*)&Qg[(size_t)(qt * 64 + r) * 64 + d0];
            Qt[(d0 + 0) * 68 + r] = v.x;
            Qt[(d0 + 1) * 68 + r] = v.y;
            Qt[(d0 + 2) * 68 + r] = v.z;
            Qt[(d0 + 3) * 68 + r] = v.w;
        }
    }

    float o[4][4], m[4], lsum[4];
#pragma unroll
    for (int i = 0; i < 4; i++) {
        m[i] = -1e30f; lsum[i] = 0.f;
#pragma unroll
        for (int j = 0; j < 4; j++) o[i][j] = 0.f;
    }

    for (int kt = 0; kt < Ll / 64; kt++) {
        {
            int r = tid >> 2, f = tid & 3;
#pragma unroll
            for (int j = 0; j < 4; j++) {
                int d0 = (f + j * 4) * 4;
                float4 kv = *(const float4*)&Kg[(size_t)(kt * 64 + r) * 64 + d0];
                Kt[(d0 + 0) * 68 + r] = kv.x;
                Kt[(d0 + 1) * 68 + r] = kv.y;
                Kt[(d0 + 2) * 68 + r] = kv.z;
                Kt[(d0 + 3) * 68 + r] = kv.w;
                float4 vv = *(const float4*)&Vg[(size_t)(kt * 64 + r) * 64 + d0];
                *(float4*)&Vs[r * 68 + d0] = vv;
            }
            if (tid < 64)
                mk[tid] = mask[b * Ll + kt * 64 + tid] ? 0.0f : -1e30f;
        }
        __syncthreads();

        // S = Q K^T (4x4 per thread)
        float s[4][4];
#pragma unroll
        for (int i = 0; i < 4; i++)
#pragma unroll
            for (int j = 0; j < 4; j++) s[i][j] = 0.f;

#pragma unroll 16
        for (int d = 0; d < 64; d++) {
            float4 qa = *(float4*)&Qt[d * 68 + ty * 4];
            float4 kb = *(float4*)&Kt[d * 68 + tx * 4];
            float aq[4] = {qa.x, qa.y, qa.z, qa.w};
            float bk[4] = {kb.x, kb.y, kb.z, kb.w};
#pragma unroll
            for (int i = 0; i < 4; i++)
#pragma unroll
                for (int j = 0; j < 4; j++)
                    s[i][j] = fmaf(aq[i], bk[j], s[i][j]);
        }

        float mkv[4];
#pragma unroll
        for (int j = 0; j < 4; j++) mkv[j] = mk[tx * 4 + j];

        // Online softmax per row (reduce across the 16 column-threads)
#pragma unroll
        for (int i = 0; i < 4; i++) {
#pragma unroll
            for (int j = 0; j < 4; j++) s[i][j] = s[i][j] * ATT_SCALE + mkv[j];
            float mx = fmaxf(fmaxf(s[i][0], s[i][1]), fmaxf(s[i][2], s[i][3]));
            for (int ofs = 8; ofs > 0; ofs >>= 1)
                mx = fmaxf(mx, __shfl_xor_sync(0xffffffffu, mx, ofs));
            float mnew = fmaxf(m[i], mx);
            float alpha = __expf(m[i] - mnew);
            m[i] = mnew;
            float rs = 0.f;
#pragma unroll
            for (int j = 0; j < 4; j++) { s[i][j] = __expf(s[i][j] - mnew); rs += s[i][j]; }
            for (int ofs = 8; ofs > 0; ofs >>= 1)
                rs += __shfl_xor_sync(0xffffffffu, rs, ofs);
            lsum[i] = lsum[i] * alpha + rs;
#pragma unroll
            for (int j = 0; j < 4; j++) o[i][j] *= alpha;
        }

        // Scatter P transposed (k-major) for the PV pass
#pragma unroll
        for (int j = 0; j < 4; j++)
#pragma unroll
            for (int i = 0; i < 4; i++)
                Pt[(tx * 4 + j) * 68 + ty * 4 + i] = s[i][j];
        __syncthreads();

        // O += P V
#pragma unroll 16
        for (int k = 0; k < 64; k++) {
            float4 pa = *(float4*)&Pt[k * 68 + ty * 4];
            float4 vb = *(float4*)&Vs[k * 68 + tx * 4];
            float ap[4] = {pa.x, pa.y, pa.z, pa.w};
            float bv[4] = {vb.x, vb.y, vb.z, vb.w};
#pragma unroll
            for (int i = 0; i < 4; i++)
#pragma unroll
                for (int j = 0; j < 4; j++)
                    o[i][j] = fmaf(ap[i], bv[j], o[i][j]);
        }
        __syncthreads();
    }

    // Finalize and write in [token][h*64+hd] layout for the O-projection
#pragma unroll
    for (int i = 0; i < 4; i++) {
        float inv = 1.0f / lsum[i];
        int tok = b * Ll + qt * 64 + ty * 4 + i;
        float4 r4 = make_float4(o[i][0] * inv, o[i][1] * inv, o[i][2] * inv, o[i][3] * inv);
        *(float4*)&g_ao[(size_t)tok * Dd + h * 64 + tx * 4] = r4;
    }
}

// ---------------------------------------------------------------------------
extern "C" void kernel_launch(void* const* d_in, const int* in_sizes, int n_in,
                              void* d_out, int out_size)
{
    const float* x    = (const float*)d_in[0];
    const float* rc   = (const float*)d_in[1];
    const float* rs   = (const float*)d_in[2];
    const float* wqkv = (const float*)d_in[3];
    const float* wo   = (const float*)d_in[4];
    const int*   mask = (const int*)d_in[5];
    float* out = (float*)d_out;

    float *qkv_p, *ao_p;
    cudaGetSymbolAddress((void**)&qkv_p, g_qkv);
    cudaGetSymbolAddress((void**)&ao_p, g_ao);

    dim3 blk(256);

    // 1) QKV projection: [4096,1024] @ [1024,3072]
    sgemm128<<<dim3(3 * Dd / 128, NT / 128), blk>>>(x, wqkv, qkv_p, NT, 3 * Dd, Dd);

    // 2) RoPE + head-major transpose
    rope_kernel<<<(NT * Hh * 32) / 256, blk>>>(rc, rs);

    // 3) Flash attention
    const int fsm = 4 * 64 * 68 * (int)sizeof(float);   // 69632 B
    cudaFuncSetAttribute((const void*)flash_kernel,
                         cudaFuncAttributeMaxDynamicSharedMemorySize, fsm);
    flash_kernel<<<dim3(Ll / 64, Hh, Bb), blk, fsm>>>(mask);

    // 4) Output projection: [4096,1024] @ [1024,1024]
    sgemm128<<<dim3(Dd / 128, NT / 128), blk>>>(ao_p, wo, out, NT, Dd, Dd);
}

// round 3
// speedup vs baseline: 1.3071x; 1.3071x over previous
#include <cuda_runtime.h>
#include <cuda_bf16.h>
#include <math.h>
#include <stdint.h>

#define Bb 2
#define Ll 2048
#define Dd 1024
#define Hh 16
#define NT (Bb*Ll)          // 4096 tokens
#define ATT_SCALE 0.125f    // 1/sqrt(64)

// ---------------------------------------------------------------------------
// Scratch (device globals — allocation-free per harness rules)
// ---------------------------------------------------------------------------
__device__ float g_qkv[(size_t)NT * 3 * Dd];   // [token][3*D]
__device__ float g_q[(size_t)NT * Dd];         // [b][h][l][hd]
__device__ float g_k[(size_t)NT * Dd];
__device__ float g_v[(size_t)NT * Dd];
__device__ float g_ao[(size_t)NT * Dd];        // [token][h*64+hd]

__device__ __nv_bfloat16 g_xhi[(size_t)NT * Dd];
__device__ __nv_bfloat16 g_xlo[(size_t)NT * Dd];
__device__ __nv_bfloat16 g_aohi[(size_t)NT * Dd];
__device__ __nv_bfloat16 g_aolo[(size_t)NT * Dd];
__device__ __nv_bfloat16 g_wqTh[(size_t)3 * Dd * Dd];   // W_qkv^T [3072][1024]
__device__ __nv_bfloat16 g_wqTl[(size_t)3 * Dd * Dd];
__device__ __nv_bfloat16 g_woTh[(size_t)Dd * Dd];       // W_o^T [1024][1024]
__device__ __nv_bfloat16 g_woTl[(size_t)Dd * Dd];

// ---------------------------------------------------------------------------
// helpers
// ---------------------------------------------------------------------------
__device__ __forceinline__ uint32_t smem_u32(const void* p) {
    uint32_t a;
    asm("{ .reg .u64 t; cvta.to.shared.u64 t, %1; cvt.u32.u64 %0, t; }"
        : "=r"(a) : "l"(p));
    return a;
}
__device__ __forceinline__ void ldsm4(uint32_t* r, uint32_t addr) {
    asm volatile("ldmatrix.sync.aligned.m8n8.x4.shared.b16 {%0,%1,%2,%3}, [%4];"
        : "=r"(r[0]), "=r"(r[1]), "=r"(r[2]), "=r"(r[3]) : "r"(addr));
}
__device__ __forceinline__ void mma16816(float* d, const uint32_t* a, const uint32_t* b) {
    asm volatile("mma.sync.aligned.m16n8k16.row.col.f32.bf16.bf16.f32 "
        "{%0,%1,%2,%3}, {%4,%5,%6,%7}, {%8,%9}, {%0,%1,%2,%3};"
        : "+f"(d[0]), "+f"(d[1]), "+f"(d[2]), "+f"(d[3])
        : "r"(a[0]), "r"(a[1]), "r"(a[2]), "r"(a[3]), "r"(b[0]), "r"(b[1]));
}
__device__ __forceinline__ void cp_async16(uint32_t sdst, const void* gsrc) {
    asm volatile("cp.async.cg.shared.global [%0], [%1], 16;" :: "r"(sdst), "l"(gsrc));
}
#define CP_COMMIT() asm volatile("cp.async.commit_group;" ::: "memory")
#define CP_WAIT0()  asm volatile("cp.async.wait_group 0;" ::: "memory")

// ---------------------------------------------------------------------------
// split fp32 -> bf16 hi/lo (same layout)
// ---------------------------------------------------------------------------
__global__ void __launch_bounds__(256) split_hilo(const float* __restrict__ in,
                                                  __nv_bfloat16* __restrict__ hi,
                                                  __nv_bfloat16* __restrict__ lo)
{
    int i = blockIdx.x * 256 + threadIdx.x;     // over n/4
    float4 v = ((const float4*)in)[i];
    __nv_bfloat16 hx = __float2bfloat16_rn(v.x);
    __nv_bfloat16 hy = __float2bfloat16_rn(v.y);
    __nv_bfloat16 hz = __float2bfloat16_rn(v.z);
    __nv_bfloat16 hw = __float2bfloat16_rn(v.w);
    __nv_bfloat162* h2 = (__nv_bfloat162*)hi;
    __nv_bfloat162* l2 = (__nv_bfloat162*)lo;
    h2[2 * i]     = __nv_bfloat162(hx, hy);
    h2[2 * i + 1] = __nv_bfloat162(hz, hw);
    l2[2 * i]     = __nv_bfloat162(__float2bfloat16_rn(v.x - __bfloat162float(hx)),
                                   __float2bfloat16_rn(v.y - __bfloat162float(hy)));
    l2[2 * i + 1] = __nv_bfloat162(__float2bfloat16_rn(v.z - __bfloat162float(hz)),
                                   __float2bfloat16_rn(v.w - __bfloat162float(hw)));
}

// ---------------------------------------------------------------------------
// split + transpose: W[K][N] fp32 -> hiT/loT [N][K] bf16
// ---------------------------------------------------------------------------
__global__ void __launch_bounds__(256) splitT(const float* __restrict__ W,
                                              __nv_bfloat16* __restrict__ hiT,
                                              __nv_bfloat16* __restrict__ loT,
                                              int K, int N)
{
    __shared__ float t[32][33];
    int n0 = blockIdx.x * 32, k0 = blockIdx.y * 32;
    int tx = threadIdx.x, ty = threadIdx.y;
#pragma unroll
    for (int r = 0; r < 4; r++)
        t[ty + r * 8][tx] = W[(size_t)(k0 + ty + r * 8) * N + n0 + tx];
    __syncthreads();
#pragma unroll
    for (int r = 0; r < 4; r++) {
        int n = ty + r * 8;
        float v = t[tx][n];
        __nv_bfloat16 h = __float2bfloat16_rn(v);
        hiT[(size_t)(n0 + n) * K + k0 + tx] = h;
        loT[(size_t)(n0 + n) * K + k0 + tx] =
            __float2bfloat16_rn(v - __bfloat162float(h));
    }
}

// ---------------------------------------------------------------------------
// HMMA GEMM: C[M,N] = (Ahi+Alo)[M,K] @ (Bhi+Blo)[N,K]^T   (3-term split)
// CTA tile 128x128, K-chunk 32, 2-stage cp.async double buffer.
// 8 warps: warp (wm = wid&1, wn = wid>>1) owns rows wm*64..+64, cols wn*32..+32.
// Per k16: 16 m16n8k16 MMAs per term, 3 terms.
// smem tile: 128 rows x 40 bf16 (80B row stride, ldmatrix conflict-free).
// ---------------------------------------------------------------------------
#define ROWB 80u
#define TILEB (128u * ROWB)          // 10240 B per matrix tile
#define STAGEB (4u * TILEB)          // 40960 B per stage

__global__ void __launch_bounds__(256) gemm_mma(const __nv_bfloat16* __restrict__ Ahi,
                                                const __nv_bfloat16* __restrict__ Alo,
                                                const __nv_bfloat16* __restrict__ Bhi,
                                                const __nv_bfloat16* __restrict__ Blo,
                                                float* __restrict__ C,
                                                int M, int N, int K)
{
    extern __shared__ char gsm[];
    const uint32_t sb = smem_u32(gsm);

    const int tid = threadIdx.x;
    const int wid = tid >> 5, lane = tid & 31;
    const int tile_n = blockIdx.x * 128, tile_m = blockIdx.y * 128;
    const int wm = wid & 1, wn = wid >> 1;
    const int NC = K >> 5;

    const __nv_bfloat16* srcs[4] = {Ahi, Alo, Bhi, Blo};
    const int rb[4] = {tile_m, tile_m, tile_n, tile_n};

    // per-thread fixed part of the load index
    const int lrow = tid >> 2;           // 0..63 within each 256-thread group
    const int lq = tid & 3;              // 16B quarter

    auto prefetch = [&](int kc, int s) {
#pragma unroll
        for (int t = 0; t < 4; t++) {
#pragma unroll
            for (int g = 0; g < 2; g++) {
                int row = g * 64 + lrow;
                const void* gp = srcs[t] + (size_t)(rb[t] + row) * K + kc * 32 + lq * 8;
                uint32_t sp = sb + (uint32_t)s * STAGEB + t * TILEB + row * ROWB + lq * 16;
                cp_async16(sp, gp);
            }
        }
        CP_COMMIT();
    };

    float acc[4][4][4];
#pragma unroll
    for (int mi = 0; mi < 4; mi++)
#pragma unroll
        for (int ni = 0; ni < 4; ni++)
#pragma unroll
            for (int e = 0; e < 4; e++) acc[mi][ni][e] = 0.f;

    prefetch(0, 0);

    // ldmatrix address components
    const uint32_t a_row = (uint32_t)(lane & 15);
    const uint32_t a_kgrp = (uint32_t)(lane >> 4) * 16;   // bytes
    const uint32_t b_n = (uint32_t)((lane & 7) + ((lane >> 4) << 3));
    const uint32_t b_kgrp = (uint32_t)((lane >> 3) & 1) * 16;

    for (int kc = 0; kc < NC; kc++) {
        const int s = kc & 1;
        CP_WAIT0();
        __syncthreads();
        if (kc + 1 < NC) prefetch(kc + 1, s ^ 1);

        const uint32_t sA  = sb + (uint32_t)s * STAGEB;
        const uint32_t sAl = sA + TILEB;
        const uint32_t sB  = sA + 2 * TILEB;
        const uint32_t sBl = sA + 3 * TILEB;

#pragma unroll
        for (int k16 = 0; k16 < 2; k16++) {
            const uint32_t kb = (uint32_t)k16 * 32;
            uint32_t ah[4][4], al[4][4], bh[4][2], bl[4][2];
#pragma unroll
            for (int mi = 0; mi < 4; mi++) {
                uint32_t off = (uint32_t)(wm * 64 + mi * 16 + a_row) * ROWB + kb + a_kgrp;
                ldsm4(ah[mi], sA + off);
                ldsm4(al[mi], sAl + off);
            }
#pragma unroll
            for (int nh = 0; nh < 2; nh++) {
                uint32_t off = (uint32_t)(wn * 32 + nh * 16 + b_n) * ROWB + kb + b_kgrp;
                uint32_t r[4];
                ldsm4(r, sB + off);
                bh[nh * 2][0] = r[0]; bh[nh * 2][1] = r[1];
                bh[nh * 2 + 1][0] = r[2]; bh[nh * 2 + 1][1] = r[3];
                ldsm4(r, sBl + off);
                bl[nh * 2][0] = r[0]; bl[nh * 2][1] = r[1];
                bl[nh * 2 + 1][0] = r[2]; bl[nh * 2 + 1][1] = r[3];
            }
#pragma unroll
            for (int mi = 0; mi < 4; mi++)
#pragma unroll
                for (int ni = 0; ni < 4; ni++)
                    mma16816(acc[mi][ni], ah[mi], bh[ni]);
#pragma unroll
            for (int mi = 0; mi < 4; mi++)
#pragma unroll
                for (int ni = 0; ni < 4; ni++)
                    mma16816(acc[mi][ni], ah[mi], bl[ni]);
#pragma unroll
            for (int mi = 0; mi < 4; mi++)
#pragma unroll
                for (int ni = 0; ni < 4; ni++)
                    mma16816(acc[mi][ni], al[mi], bh[ni]);
        }
    }

    // epilogue: D frag -> C (fp32)
#pragma unroll
    for (int mi = 0; mi < 4; mi++) {
        const int r0 = tile_m + wm * 64 + mi * 16 + (lane >> 2);
#pragma unroll
        for (int ni = 0; ni < 4; ni++) {
            const int c = tile_n + wn * 32 + ni * 8 + 2 * (lane & 3);
            *(float2*)&C[(size_t)r0 * N + c] =
                make_float2(acc[mi][ni][0], acc[mi][ni][1]);
            *(float2*)&C[(size_t)(r0 + 8) * N + c] =
                make_float2(acc[mi][ni][2], acc[mi][ni][3]);
        }
    }
}

// ---------------------------------------------------------------------------
// RoPE + transpose to head-major [b][h][l][hd] for q,k (roped) and v (copy).
// ---------------------------------------------------------------------------
__global__ void __launch_bounds__(256) rope_kernel(const float* __restrict__ cosb,
                                                   const float* __restrict__ sinb)
{
    int idx = blockIdx.x * blockDim.x + threadIdx.x;   // < NT*Hh*32
    int i = idx & 31;
    int h = (idx >> 5) & 15;
    int t = idx >> 9;
    int b = t >> 11;
    int l = t & (Ll - 1);

    float c = cosb[(size_t)t * (Dd / 2) + h * 32 + i];
    float s = sinb[(size_t)t * (Dd / 2) + h * 32 + i];

    const float* row = &g_qkv[(size_t)t * 3 * Dd];
    float q1 = row[h * 64 + i],            q2 = row[h * 64 + 32 + i];
    float k1 = row[Dd + h * 64 + i],       k2 = row[Dd + h * 64 + 32 + i];
    float v1 = row[2 * Dd + h * 64 + i],   v2 = row[2 * Dd + h * 64 + 32 + i];

    size_t o = ((size_t)(b * Hh + h) * Ll + l) * 64;
    g_q[o + i]      = q1 * c - q2 * s;
    g_q[o + 32 + i] = q1 * s + q2 * c;
    g_k[o + i]      = k1 * c - k2 * s;
    g_k[o + 32 + i] = k1 * s + k2 * c;
    g_v[o + i]      = v1;
    g_v[o + 32 + i] = v2;
}

// ---------------------------------------------------------------------------
// Flash attention fp32 (unchanged — known correct)
// ---------------------------------------------------------------------------
__global__ void __launch_bounds__(256) flash_kernel(const int* __restrict__ mask)
{
    extern __shared__ float fsh[];
    float* Qt = fsh;
    float* Kt = Qt + 64 * 68;
    float* Vs = Kt + 64 * 68;
    float* Pt = Vs + 64 * 68;
    __shared__ float mk[64];

    const int qt = blockIdx.x, h = blockIdx.y, b = blockIdx.z;
    const int tid = threadIdx.x;
    const int tx = tid & 15, ty = tid >> 4;

    const size_t head_off = (size_t)(b * Hh + h) * Ll * 64;
    const float* Qg = g_q + head_off;
    const float* Kg = g_k + head_off;
    const float* Vg = g_v + head_off;

    {
        int r = tid >> 2, f = tid & 3;
#pragma unroll
        for (int j = 0; j < 4; j++) {
            int d0 = (f + j * 4) * 4;
            float4 v = *(const float4*)&Qg[(size_t)(qt * 64 + r) * 64 + d0];
            Qt[(d0 + 0) * 68 + r] = v.x;
            Qt[(d0 + 1) * 68 + r] = v.y;
            Qt[(d0 + 2) * 68 + r] = v.z;
            Qt[(d0 + 3) * 68 + r] = v.w;
        }
    }

    float o[4][4], m[4], lsum[4];
#pragma unroll
    for (int i = 0; i < 4; i++) {
        m[i] = -1e30f; lsum[i] = 0.f;
#pragma unroll
        for (int j = 0; j < 4; j++) o[i][j] = 0.f;
    }

    for (int kt = 0; kt < Ll / 64; kt++) {
        {
            int r = tid >> 2, f = tid & 3;
#pragma unroll
            for (int j = 0; j < 4; j++) {
                int d0 = (f + j * 4) * 4;
                float4 kv = *(const float4*)&Kg[(size_t)(kt * 64 + r) * 64 + d0];
                Kt[(d0 + 0) * 68 + r] = kv.x;
                Kt[(d0 + 1) * 68 + r] = kv.y;
                Kt[(d0 + 2) * 68 + r] = kv.z;
                Kt[(d0 + 3) * 68 + r] = kv.w;
                float4 vv = *(const float4*)&Vg[(size_t)(kt * 64 + r) * 64 + d0];
                *(float4*)&Vs[r * 68 + d0] = vv;
            }
            if (tid < 64)
                mk[tid] = mask[b * Ll + kt * 64 + tid] ? 0.0f : -1e30f;
        }
        __syncthreads();

        float s[4][4];
#pragma unroll
        for (int i = 0; i < 4; i++)
#pragma unroll
            for (int j = 0; j < 4; j++) s[i][j] = 0.f;

#pragma unroll 16
        for (int d = 0; d < 64; d++) {
            float4 qa = *(float4*)&Qt[d * 68 + ty * 4];
            float4 kb = *(float4*)&Kt[d * 68 + tx * 4];
            float aq[4] = {qa.x, qa.y, qa.z, qa.w};
            float bk[4] = {kb.x, kb.y, kb.z, kb.w};
#pragma unroll
            for (int i = 0; i < 4; i++)
#pragma unroll
                for (int j = 0; j < 4; j++)
                    s[i][j] = fmaf(aq[i], bk[j], s[i][j]);
        }

        float mkv[4];
#pragma unroll
        for (int j = 0; j < 4; j++) mkv[j] = mk[tx * 4 + j];

#pragma unroll
        for (int i = 0; i < 4; i++) {
#pragma unroll
            for (int j = 0; j < 4; j++) s[i][j] = s[i][j] * ATT_SCALE + mkv[j];
            float mx = fmaxf(fmaxf(s[i][0], s[i][1]), fmaxf(s[i][2], s[i][3]));
            for (int ofs = 8; ofs > 0; ofs >>= 1)
                mx = fmaxf(mx, __shfl_xor_sync(0xffffffffu, mx, ofs));
            float mnew = fmaxf(m[i], mx);
            float alpha = __expf(m[i] - mnew);
            m[i] = mnew;
            float rs = 0.f;
#pragma unroll
            for (int j = 0; j < 4; j++) { s[i][j] = __expf(s[i][j] - mnew); rs += s[i][j]; }
            for (int ofs = 8; ofs > 0; ofs >>= 1)
                rs += __shfl_xor_sync(0xffffffffu, rs, ofs);
            lsum[i] = lsum[i] * alpha + rs;
#pragma unroll
            for (int j = 0; j < 4; j++) o[i][j] *= alpha;
        }

#pragma unroll
        for (int j = 0; j < 4; j++)
#pragma unroll
            for (int i = 0; i < 4; i++)
                Pt[(tx * 4 + j) * 68 + ty * 4 + i] = s[i][j];
        __syncthreads();

#pragma unroll 16
        for (int k = 0; k < 64; k++) {
            float4 pa = *(float4*)&Pt[k * 68 + ty * 4];
            float4 vb = *(float4*)&Vs[k * 68 + tx * 4];
            float ap[4] = {pa.x, pa.y, pa.z, pa.w};
            float bv[4] = {vb.x, vb.y, vb.z, vb.w};
#pragma unroll
            for (int i = 0; i < 4; i++)
#pragma unroll
                for (int j = 0; j < 4; j++)
                    o[i][j] = fmaf(ap[i], bv[j], o[i][j]);
        }
        __syncthreads();
    }

#pragma unroll
    for (int i = 0; i < 4; i++) {
        float inv = 1.0f / lsum[i];
        int tok = b * Ll + qt * 64 + ty * 4 + i;
        float4 r4 = make_float4(o[i][0] * inv, o[i][1] * inv, o[i][2] * inv, o[i][3] * inv);
        *(float4*)&g_ao[(size_t)tok * Dd + h * 64 + tx * 4] = r4;
    }
}

// ---------------------------------------------------------------------------
extern "C" void kernel_launch(void* const* d_in, const int* in_sizes, int n_in,
                              void* d_out, int out_size)
{
    const float* x    = (const float*)d_in[0];
    const float* rc   = (const float*)d_in[1];
    const float* rs   = (const float*)d_in[2];
    const float* wqkv = (const float*)d_in[3];
    const float* wo   = (const float*)d_in[4];
    const int*   mask = (const int*)d_in[5];
    float* out = (float*)d_out;

    float *qkv_p, *ao_p;
    __nv_bfloat16 *xhi, *xlo, *aohi, *aolo, *wqTh, *wqTl, *woTh, *woTl;
    cudaGetSymbolAddress((void**)&qkv_p, g_qkv);
    cudaGetSymbolAddress((void**)&ao_p, g_ao);
    cudaGetSymbolAddress((void**)&xhi, g_xhi);
    cudaGetSymbolAddress((void**)&xlo, g_xlo);
    cudaGetSymbolAddress((void**)&aohi, g_aohi);
    cudaGetSymbolAddress((void**)&aolo, g_aolo);
    cudaGetSymbolAddress((void**)&wqTh, g_wqTh);
    cudaGetSymbolAddress((void**)&wqTl, g_wqTl);
    cudaGetSymbolAddress((void**)&woTh, g_woTh);
    cudaGetSymbolAddress((void**)&woTl, g_woTl);

    const int GSM = 2 * (int)STAGEB;    // 81920
    cudaFuncSetAttribute((const void*)gemm_mma,
                         cudaFuncAttributeMaxDynamicSharedMemorySize, GSM);
    const int fsm = 4 * 64 * 68 * (int)sizeof(float);
    cudaFuncSetAttribute((const void*)flash_kernel,
                         cudaFuncAttributeMaxDynamicSharedMemorySize, fsm);

    dim3 blk(256);

    // 0) splits
    split_hilo<<<(NT * Dd / 4) / 256, blk>>>(x, xhi, xlo);
    splitT<<<dim3(3 * Dd / 32, Dd / 32), dim3(32, 8)>>>(wqkv, wqTh, wqTl, Dd, 3 * Dd);
    splitT<<<dim3(Dd / 32, Dd / 32), dim3(32, 8)>>>(wo, woTh, woTl, Dd, Dd);

    // 1) QKV projection (HMMA): [4096,1024] @ [1024,3072]
    gemm_mma<<<dim3(3 * Dd / 128, NT / 128), blk, GSM>>>(xhi, xlo, wqTh, wqTl,
                                                         qkv_p, NT, 3 * Dd, Dd);

    // 2) RoPE + head-major transpose
    rope_kernel<<<(NT * Hh * 32) / 256, blk>>>(rc, rs);

    // 3) Flash attention (fp32 SIMT)
    flash_kernel<<<dim3(Ll / 64, Hh, Bb), blk, fsm>>>(mask);

    // 4) Output projection (HMMA)
    split_hilo<<<(NT * Dd / 4) / 256, blk>>>(ao_p, aohi, aolo);
    gemm_mma<<<dim3(Dd / 128, NT / 128), blk, GSM>>>(aohi, aolo, woTh, woTl,
                                                     out, NT, Dd, Dd);
}

// round 5
// speedup vs baseline: 2.7234x; 2.0835x over previous
#include <cuda_runtime.h>
#include <cuda_bf16.h>
#include <math.h>
#include <stdint.h>

#define Bb 2
#define Ll 2048
#define Dd 1024
#define Hh 16
#define NT (Bb*Ll)          // 4096 tokens
#define ATT_SCALE 0.125f    // 1/sqrt(64)

// ---------------------------------------------------------------------------
// Scratch (device globals — allocation-free per harness rules)
// ---------------------------------------------------------------------------
__device__ float g_qkv[(size_t)NT * 3 * Dd];   // [token][3*D]

__device__ __nv_bfloat16 g_xhi[(size_t)NT * Dd];
__device__ __nv_bfloat16 g_xlo[(size_t)NT * Dd];
__device__ __nv_bfloat16 g_aohi[(size_t)NT * Dd];   // attn out [token][h*64+d]
__device__ __nv_bfloat16 g_aolo[(size_t)NT * Dd];
__device__ __nv_bfloat16 g_wqTh[(size_t)3 * Dd * Dd];
__device__ __nv_bfloat16 g_wqTl[(size_t)3 * Dd * Dd];
__device__ __nv_bfloat16 g_woTh[(size_t)Dd * Dd];
__device__ __nv_bfloat16 g_woTl[(size_t)Dd * Dd];
// head-major [b][h][l][64] bf16 hi/lo
__device__ __nv_bfloat16 g_qhi[(size_t)NT * Dd];
__device__ __nv_bfloat16 g_qlo[(size_t)NT * Dd];
__device__ __nv_bfloat16 g_khi[(size_t)NT * Dd];
__device__ __nv_bfloat16 g_klo[(size_t)NT * Dd];
__device__ __nv_bfloat16 g_vhi[(size_t)NT * Dd];
__device__ __nv_bfloat16 g_vlo[(size_t)NT * Dd];

// ---------------------------------------------------------------------------
// helpers
// ---------------------------------------------------------------------------
__device__ __forceinline__ uint32_t smem_u32(const void* p) {
    uint32_t a;
    asm("{ .reg .u64 t; cvta.to.shared.u64 t, %1; cvt.u32.u64 %0, t; }"
        : "=r"(a) : "l"(p));
    return a;
}
__device__ __forceinline__ void ldsm4(uint32_t* r, uint32_t addr) {
    asm volatile("ldmatrix.sync.aligned.m8n8.x4.shared.b16 {%0,%1,%2,%3}, [%4];"
        : "=r"(r[0]), "=r"(r[1]), "=r"(r[2]), "=r"(r[3]) : "r"(addr));
}
__device__ __forceinline__ void ldsm4t(uint32_t* r, uint32_t addr) {
    asm volatile("ldmatrix.sync.aligned.m8n8.x4.trans.shared.b16 {%0,%1,%2,%3}, [%4];"
        : "=r"(r[0]), "=r"(r[1]), "=r"(r[2]), "=r"(r[3]) : "r"(addr));
}
__device__ __forceinline__ void mma16816(float* d, const uint32_t* a, const uint32_t* b) {
    asm volatile("mma.sync.aligned.m16n8k16.row.col.f32.bf16.bf16.f32 "
        "{%0,%1,%2,%3}, {%4,%5,%6,%7}, {%8,%9}, {%0,%1,%2,%3};"
        : "+f"(d[0]), "+f"(d[1]), "+f"(d[2]), "+f"(d[3])
        : "r"(a[0]), "r"(a[1]), "r"(a[2]), "r"(a[3]), "r"(b[0]), "r"(b[1]));
}
__device__ __forceinline__ void cp_async16(uint32_t sdst, const void* gsrc) {
    asm volatile("cp.async.cg.shared.global [%0], [%1], 16;" :: "r"(sdst), "l"(gsrc));
}
#define CP_COMMIT() asm volatile("cp.async.commit_group;" ::: "memory")
#define CP_WAIT0()  asm volatile("cp.async.wait_group 0;" ::: "memory")

__device__ __forceinline__ uint32_t packbf(float a, float b) {
    __nv_bfloat162 h = __floats2bfloat162_rn(a, b);
    return *(uint32_t*)&h;
}

// ---------------------------------------------------------------------------
// split fp32 -> bf16 hi/lo
// ---------------------------------------------------------------------------
__global__ void __launch_bounds__(256) split_hilo(const float* __restrict__ in,
                                                  __nv_bfloat16* __restrict__ hi,
                                                  __nv_bfloat16* __restrict__ lo)
{
    int i = blockIdx.x * 256 + threadIdx.x;
    float4 v = ((const float4*)in)[i];
    __nv_bfloat16 hx = __float2bfloat16_rn(v.x);
    __nv_bfloat16 hy = __float2bfloat16_rn(v.y);
    __nv_bfloat16 hz = __float2bfloat16_rn(v.z);
    __nv_bfloat16 hw = __float2bfloat16_rn(v.w);
    __nv_bfloat162* h2 = (__nv_bfloat162*)hi;
    __nv_bfloat162* l2 = (__nv_bfloat162*)lo;
    h2[2 * i]     = __nv_bfloat162(hx, hy);
    h2[2 * i + 1] = __nv_bfloat162(hz, hw);
    l2[2 * i]     = __nv_bfloat162(__float2bfloat16_rn(v.x - __bfloat162float(hx)),
                                   __float2bfloat16_rn(v.y - __bfloat162float(hy)));
    l2[2 * i + 1] = __nv_bfloat162(__float2bfloat16_rn(v.z - __bfloat162float(hz)),
                                   __float2bfloat16_rn(v.w - __bfloat162float(hw)));
}

// ---------------------------------------------------------------------------
// split + transpose: W[K][N] fp32 -> hiT/loT [N][K] bf16
// ---------------------------------------------------------------------------
__global__ void __launch_bounds__(256) splitT(const float* __restrict__ W,
                                              __nv_bfloat16* __restrict__ hiT,
                                              __nv_bfloat16* __restrict__ loT,
                                              int K, int N)
{
    __shared__ float t[32][33];
    int n0 = blockIdx.x * 32, k0 = blockIdx.y * 32;
    int tx = threadIdx.x, ty = threadIdx.y;
#pragma unroll
    for (int r = 0; r < 4; r++)
        t[ty + r * 8][tx] = W[(size_t)(k0 + ty + r * 8) * N + n0 + tx];
    __syncthreads();
#pragma unroll
    for (int r = 0; r < 4; r++) {
        int n = ty + r * 8;
        float v = t[tx][n];
        __nv_bfloat16 h = __float2bfloat16_rn(v);
        hiT[(size_t)(n0 + n) * K + k0 + tx] = h;
        loT[(size_t)(n0 + n) * K + k0 + tx] =
            __float2bfloat16_rn(v - __bfloat162float(h));
    }
}

// ---------------------------------------------------------------------------
// HMMA GEMM (occupancy 2)
// ---------------------------------------------------------------------------
#define ROWB 80u
#define TILEB (128u * ROWB)
#define STAGEB (4u * TILEB)

__global__ void __launch_bounds__(256, 2) gemm_mma(const __nv_bfloat16* __restrict__ Ahi,
                                                   const __nv_bfloat16* __restrict__ Alo,
                                                   const __nv_bfloat16* __restrict__ Bhi,
                                                   const __nv_bfloat16* __restrict__ Blo,
                                                   float* __restrict__ C,
                                                   int M, int N, int K)
{
    extern __shared__ char gsm[];
    const uint32_t sb = smem_u32(gsm);

    const int tid = threadIdx.x;
    const int wid = tid >> 5, lane = tid & 31;
    const int tile_n = blockIdx.x * 128, tile_m = blockIdx.y * 128;
    const int wm = wid & 1, wn = wid >> 1;
    const int NC = K >> 5;

    const __nv_bfloat16* srcs[4] = {Ahi, Alo, Bhi, Blo};
    const int rb[4] = {tile_m, tile_m, tile_n, tile_n};

    const int lrow = tid >> 2;
    const int lq = tid & 3;

    auto prefetch = [&](int kc, int s) {
#pragma unroll
        for (int t = 0; t < 4; t++) {
#pragma unroll
            for (int g = 0; g < 2; g++) {
                int row = g * 64 + lrow;
                const void* gp = srcs[t] + (size_t)(rb[t] + row) * K + kc * 32 + lq * 8;
                uint32_t sp = sb + (uint32_t)s * STAGEB + t * TILEB + row * ROWB + lq * 16;
                cp_async16(sp, gp);
            }
        }
        CP_COMMIT();
    };

    float acc[4][4][4];
#pragma unroll
    for (int mi = 0; mi < 4; mi++)
#pragma unroll
        for (int ni = 0; ni < 4; ni++)
#pragma unroll
            for (int e = 0; e < 4; e++) acc[mi][ni][e] = 0.f;

    prefetch(0, 0);

    const uint32_t a_row = (uint32_t)(lane & 15);
    const uint32_t a_kgrp = (uint32_t)(lane >> 4) * 16;
    const uint32_t b_n = (uint32_t)((lane & 7) + ((lane >> 4) << 3));
    const uint32_t b_kgrp = (uint32_t)((lane >> 3) & 1) * 16;

    for (int kc = 0; kc < NC; kc++) {
        const int s = kc & 1;
        CP_WAIT0();
        __syncthreads();
        if (kc + 1 < NC) prefetch(kc + 1, s ^ 1);

        const uint32_t sA  = sb + (uint32_t)s * STAGEB;
        const uint32_t sAl = sA + TILEB;
        const uint32_t sB  = sA + 2 * TILEB;
        const uint32_t sBl = sA + 3 * TILEB;

#pragma unroll
        for (int k16 = 0; k16 < 2; k16++) {
            const uint32_t kb = (uint32_t)k16 * 32;
            uint32_t ah[4][4], al[4][4], bh[4][2], bl[4][2];
#pragma unroll
            for (int mi = 0; mi < 4; mi++) {
                uint32_t off = (uint32_t)(wm * 64 + mi * 16 + a_row) * ROWB + kb + a_kgrp;
                ldsm4(ah[mi], sA + off);
                ldsm4(al[mi], sAl + off);
            }
#pragma unroll
            for (int nh = 0; nh < 2; nh++) {
                uint32_t off = (uint32_t)(wn * 32 + nh * 16 + b_n) * ROWB + kb + b_kgrp;
                uint32_t r[4];
                ldsm4(r, sB + off);
                bh[nh * 2][0] = r[0]; bh[nh * 2][1] = r[1];
                bh[nh * 2 + 1][0] = r[2]; bh[nh * 2 + 1][1] = r[3];
                ldsm4(r, sBl + off);
                bl[nh * 2][0] = r[0]; bl[nh * 2][1] = r[1];
                bl[nh * 2 + 1][0] = r[2]; bl[nh * 2 + 1][1] = r[3];
            }
#pragma unroll
            for (int mi = 0; mi < 4; mi++)
#pragma unroll
                for (int ni = 0; ni < 4; ni++)
                    mma16816(acc[mi][ni], ah[mi], bh[ni]);
#pragma unroll
            for (int mi = 0; mi < 4; mi++)
#pragma unroll
                for (int ni = 0; ni < 4; ni++)
                    mma16816(acc[mi][ni], ah[mi], bl[ni]);
#pragma unroll
            for (int mi = 0; mi < 4; mi++)
#pragma unroll
                for (int ni = 0; ni < 4; ni++)
                    mma16816(acc[mi][ni], al[mi], bh[ni]);
        }
    }

#pragma unroll
    for (int mi = 0; mi < 4; mi++) {
        const int r0 = tile_m + wm * 64 + mi * 16 + (lane >> 2);
#pragma unroll
        for (int ni = 0; ni < 4; ni++) {
            const int c = tile_n + wn * 32 + ni * 8 + 2 * (lane & 3);
            *(float2*)&C[(size_t)r0 * N + c] =
                make_float2(acc[mi][ni][0], acc[mi][ni][1]);
            *(float2*)&C[(size_t)(r0 + 8) * N + c] =
                make_float2(acc[mi][ni][2], acc[mi][ni][3]);
        }
    }
}

// ---------------------------------------------------------------------------
// RoPE: g_qkv fp32 -> head-major bf16 hi/lo q,k,v
// ---------------------------------------------------------------------------
__global__ void __launch_bounds__(256) rope_kernel(const float* __restrict__ cosb,
                                                   const float* __restrict__ sinb)
{
    int idx = blockIdx.x * blockDim.x + threadIdx.x;   // < NT*Hh*32
    int i = idx & 31;
    int h = (idx >> 5) & 15;
    int t = idx >> 9;
    int b = t >> 11;
    int l = t & (Ll - 1);

    float c = cosb[(size_t)t * (Dd / 2) + h * 32 + i];
    float s = sinb[(size_t)t * (Dd / 2) + h * 32 + i];

    const float* row = &g_qkv[(size_t)t * 3 * Dd];
    float q1 = row[h * 64 + i],            q2 = row[h * 64 + 32 + i];
    float k1 = row[Dd + h * 64 + i],       k2 = row[Dd + h * 64 + 32 + i];
    float v1 = row[2 * Dd + h * 64 + i],   v2 = row[2 * Dd + h * 64 + 32 + i];

    float qa = q1 * c - q2 * s, qb = q1 * s + q2 * c;
    float ka = k1 * c - k2 * s, kb = k1 * s + k2 * c;

    size_t o = ((size_t)(b * Hh + h) * Ll + l) * 64;
#define SPLIT_ST(arr_hi, arr_lo, off, val) do { \
        __nv_bfloat16 _h = __float2bfloat16_rn(val); \
        arr_hi[(o) + (off)] = _h; \
        arr_lo[(o) + (off)] = __float2bfloat16_rn((val) - __bfloat162float(_h)); \
    } while (0)
    SPLIT_ST(g_qhi, g_qlo, i,      qa);
    SPLIT_ST(g_qhi, g_qlo, 32 + i, qb);
    SPLIT_ST(g_khi, g_klo, i,      ka);
    SPLIT_ST(g_khi, g_klo, 32 + i, kb);
    SPLIT_ST(g_vhi, g_vlo, i,      v1);
    SPLIT_ST(g_vhi, g_vlo, 32 + i, v2);
#undef SPLIT_ST
}

// ---------------------------------------------------------------------------
// HMMA flash attention.
// CTA: 128 q-rows of one (b,h). 8 warps; warp w owns q rows w*16..+16.
// KV tile 64. S = QK^T and O += PV via m16n8k16 bf16 (3-term hi/lo splits).
// smem: 2 stages x {Khi,Klo,Vhi,Vlo}[64 x 144B]; Q staged once in stage1 area.
// ---------------------------------------------------------------------------
#define FROWB 144u
#define FMATB (64u * FROWB)     // 9216
#define FSTAGEB (4u * FMATB)    // 36864
#define FSMEM (2u * FSTAGEB)    // 73728

__global__ void __launch_bounds__(256) flash_mma(const int* __restrict__ mask)
{
    extern __shared__ char fsm_[];
    const uint32_t sb = smem_u32(fsm_);
    __shared__ float mks[2][64];

    const int qt = blockIdx.x, h = blockIdx.y, b = blockIdx.z;
    const int tid = threadIdx.x;
    const int wid = tid >> 5, lane = tid & 31;

    const size_t hoff = (size_t)(b * Hh + h) * Ll * 64;
    const __nv_bfloat16* Khi = g_khi + hoff;
    const __nv_bfloat16* Klo = g_klo + hoff;
    const __nv_bfloat16* Vhi = g_vhi + hoff;
    const __nv_bfloat16* Vlo = g_vlo + hoff;

    // ---- prologue: stage Q (hi/lo) into stage-1 area, prefetch KV tile 0 ----
    // 2 mats x 128 rows x 8 sixteen-byte quarters = 2048 chunks
    {
        const __nv_bfloat16* Qs[2] = {g_qhi + hoff, g_qlo + hoff};
#pragma unroll
        for (int it = 0; it < 8; it++) {
            int idx = it * 256 + tid;           // 0..2047
            int mat = idx >> 10;                // 0..1
            int r = (idx >> 3) & 127;           // 0..127
            int q = idx & 7;                    // 0..7 (16B each -> 128B row)
            const void* gp = Qs[mat] + (size_t)(qt * 128 + r) * 64 + q * 8;
            uint32_t sp = sb + FSTAGEB + mat * (128u * FROWB) + r * FROWB + q * 16;
            cp_async16(sp, gp);
        }
        CP_COMMIT();
    }
    const __nv_bfloat16* kvsrc[4] = {Khi, Klo, Vhi, Vlo};
    // 4 mats x 64 rows x 8 quarters = 2048 chunks
    auto prefetch = [&](int t, int s) {
#pragma unroll
        for (int it = 0; it < 8; it++) {
            int idx = it * 256 + tid;           // 0..2047
            int mat = idx >> 9;                 // 0..3
            int r = (idx >> 3) & 63;            // 0..63
            int q = idx & 7;                    // 0..7
            const void* gp = kvsrc[mat] + (size_t)(t * 64 + r) * 64 + q * 8;
            uint32_t sp = sb + (uint32_t)s * FSTAGEB + mat * FMATB + r * FROWB + q * 16;
            cp_async16(sp, gp);
        }
        CP_COMMIT();
        if (tid < 64)
            mks[s][tid] = mask[b * Ll + t * 64 + tid] ? 0.0f : -1e30f;
    };
    prefetch(0, 0);
    CP_WAIT0();
    __syncthreads();

    // ---- extract Q fragments (register-resident for the whole kernel) ----
    uint32_t qhf[4][4], qlf[4][4];
    {
        const uint32_t qrow = (uint32_t)(lane & 15);
        const uint32_t qg = (uint32_t)(lane >> 4) * 16;
#pragma unroll
        for (int ki = 0; ki < 4; ki++) {
            uint32_t off = (uint32_t)(wid * 16 + qrow) * FROWB + ki * 32 + qg;
            ldsm4(qhf[ki], sb + FSTAGEB + off);
            ldsm4(qlf[ki], sb + FSTAGEB + 128u * FROWB + off);
        }
    }
    __syncthreads();   // done reading stage-1 area; prefetch may overwrite it

    float oacc[8][4];
#pragma unroll
    for (int ni = 0; ni < 8; ni++)
#pragma unroll
        for (int e = 0; e < 4; e++) oacc[ni][e] = 0.f;
    float m0 = -1e30f, m1 = -1e30f, l0 = 0.f, l1 = 0.f;

    const uint32_t krow = (uint32_t)((lane & 7) + ((lane >> 4) << 3));
    const uint32_t kg = (uint32_t)((lane >> 3) & 1) * 16;
    const uint32_t vrow = (uint32_t)(lane & 15);
    const uint32_t vg = (uint32_t)(lane >> 4) * 16;

    for (int t = 0; t < Ll / 64; t++) {
        const int s = t & 1;
        CP_WAIT0();
        __syncthreads();
        if (t + 1 < Ll / 64) prefetch(t + 1, s ^ 1);

        const uint32_t stK  = sb + (uint32_t)s * FSTAGEB;
        const uint32_t stKl = stK + FMATB;
        const uint32_t stV  = stK + 2 * FMATB;
        const uint32_t stVl = stK + 3 * FMATB;

        // ---- S = Q K^T ----
        float sacc[8][4];
#pragma unroll
        for (int ni = 0; ni < 8; ni++)
#pragma unroll
            for (int e = 0; e < 4; e++) sacc[ni][e] = 0.f;

#pragma unroll
        for (int nh = 0; nh < 4; nh++) {
#pragma unroll
            for (int ki = 0; ki < 4; ki++) {
                uint32_t off = (uint32_t)(nh * 16 + krow) * FROWB + ki * 32 + kg;
                uint32_t r[4], bh0[2], bh1[2], bl0[2], bl1[2];
                ldsm4(r, stK + off);
                bh0[0] = r[0]; bh0[1] = r[1]; bh1[0] = r[2]; bh1[1] = r[3];
                ldsm4(r, stKl + off);
                bl0[0] = r[0]; bl0[1] = r[1]; bl1[0] = r[2]; bl1[1] = r[3];
                mma16816(sacc[2 * nh],     qhf[ki], bh0);
                mma16816(sacc[2 * nh + 1], qhf[ki], bh1);
                mma16816(sacc[2 * nh],     qhf[ki], bl0);
                mma16816(sacc[2 * nh + 1], qhf[ki], bl1);
                mma16816(sacc[2 * nh],     qlf[ki], bh0);
                mma16816(sacc[2 * nh + 1], qlf[ki], bh1);
            }
        }

        // ---- online softmax ----
        float rmax0 = -1e30f, rmax1 = -1e30f;
        const int cq = 2 * (lane & 3);
#pragma unroll
        for (int ni = 0; ni < 8; ni++) {
            float mk0 = mks[s][ni * 8 + cq];
            float mk1 = mks[s][ni * 8 + cq + 1];
            sacc[ni][0] = sacc[ni][0] * ATT_SCALE + mk0;
            sacc[ni][1] = sacc[ni][1] * ATT_SCALE + mk1;
            sacc[ni][2] = sacc[ni][2] * ATT_SCALE + mk0;
            sacc[ni][3] = sacc[ni][3] * ATT_SCALE + mk1;
            rmax0 = fmaxf(rmax0, fmaxf(sacc[ni][0], sacc[ni][1]));
            rmax1 = fmaxf(rmax1, fmaxf(sacc[ni][2], sacc[ni][3]));
        }
        rmax0 = fmaxf(rmax0, __shfl_xor_sync(0xffffffffu, rmax0, 1));
        rmax0 = fmaxf(rmax0, __shfl_xor_sync(0xffffffffu, rmax0, 2));
        rmax1 = fmaxf(rmax1, __shfl_xor_sync(0xffffffffu, rmax1, 1));
        rmax1 = fmaxf(rmax1, __shfl_xor_sync(0xffffffffu, rmax1, 2));

        float mn0 = fmaxf(m0, rmax0), mn1 = fmaxf(m1, rmax1);
        float a0 = __expf(m0 - mn0), a1 = __expf(m1 - mn1);
        m0 = mn0; m1 = mn1;

        float rs0 = 0.f, rs1 = 0.f;
#pragma unroll
        for (int ni = 0; ni < 8; ni++) {
            sacc[ni][0] = __expf(sacc[ni][0] - mn0);
            sacc[ni][1] = __expf(sacc[ni][1] - mn0);
            sacc[ni][2] = __expf(sacc[ni][2] - mn1);
            sacc[ni][3] = __expf(sacc[ni][3] - mn1);
            rs0 += sacc[ni][0] + sacc[ni][1];
            rs1 += sacc[ni][2] + sacc[ni][3];
        }
        rs0 += __shfl_xor_sync(0xffffffffu, rs0, 1);
        rs0 += __shfl_xor_sync(0xffffffffu, rs0, 2);
        rs1 += __shfl_xor_sync(0xffffffffu, rs1, 1);
        rs1 += __shfl_xor_sync(0xffffffffu, rs1, 2);
        l0 = l0 * a0 + rs0;
        l1 = l1 * a1 + rs1;
#pragma unroll
        for (int ni = 0; ni < 8; ni++) {
            oacc[ni][0] *= a0; oacc[ni][1] *= a0;
            oacc[ni][2] *= a1; oacc[ni][3] *= a1;
        }

        // ---- O += P V ----
#pragma unroll
        for (int ki = 0; ki < 4; ki++) {
            uint32_t ph[4], pl[4];
            float* p0 = sacc[2 * ki];
            float* p1 = sacc[2 * ki + 1];
            ph[0] = packbf(p0[0], p0[1]);
            ph[1] = packbf(p0[2], p0[3]);
            ph[2] = packbf(p1[0], p1[1]);
            ph[3] = packbf(p1[2], p1[3]);
#pragma unroll
            for (int e = 0; e < 4; e++) {
                float* pp = (e < 2) ? p0 : p1;
                int b0 = (e & 1) * 2;
                float lo0 = pp[b0]     - __bfloat162float(__float2bfloat16_rn(pp[b0]));
                float lo1 = pp[b0 + 1] - __bfloat162float(__float2bfloat16_rn(pp[b0 + 1]));
                pl[e] = packbf(lo0, lo1);
            }
#pragma unroll
            for (int nh = 0; nh < 4; nh++) {
                uint32_t off = (uint32_t)(ki * 16 + vrow) * FROWB + nh * 32 + vg;
                uint32_t r[4], vh0[2], vh1[2], vl0[2], vl1[2];
                ldsm4t(r, stV + off);
                vh0[0] = r[0]; vh0[1] = r[1]; vh1[0] = r[2]; vh1[1] = r[3];
                ldsm4t(r, stVl + off);
                vl0[0] = r[0]; vl0[1] = r[1]; vl1[0] = r[2]; vl1[1] = r[3];
                mma16816(oacc[2 * nh],     ph, vh0);
                mma16816(oacc[2 * nh + 1], ph, vh1);
                mma16816(oacc[2 * nh],     ph, vl0);
                mma16816(oacc[2 * nh + 1], ph, vl1);
                mma16816(oacc[2 * nh],     pl, vh0);
                mma16816(oacc[2 * nh + 1], pl, vh1);
            }
        }
    }

    // ---- epilogue: normalize, split hi/lo, write [token][h*64+d] ----
    float inv0 = 1.0f / l0, inv1 = 1.0f / l1;
    const int tok0 = b * Ll + qt * 128 + wid * 16 + (lane >> 2);
    const int cbase = h * 64 + 2 * (lane & 3);
#pragma unroll
    for (int ni = 0; ni < 8; ni++) {
        float v00 = oacc[ni][0] * inv0, v01 = oacc[ni][1] * inv0;
        float v10 = oacc[ni][2] * inv1, v11 = oacc[ni][3] * inv1;
        size_t o0 = (size_t)tok0 * Dd + cbase + ni * 8;
        size_t o1 = (size_t)(tok0 + 8) * Dd + cbase + ni * 8;
        uint32_t h00 = packbf(v00, v01), h10 = packbf(v10, v11);
        *(uint32_t*)&g_aohi[o0] = h00;
        *(uint32_t*)&g_aohi[o1] = h10;
        __nv_bfloat162 hh0 = *(__nv_bfloat162*)&h00;
        __nv_bfloat162 hh1 = *(__nv_bfloat162*)&h10;
        *(uint32_t*)&g_aolo[o0] = packbf(v00 - __bfloat162float(hh0.x),
                                         v01 - __bfloat162float(hh0.y));
        *(uint32_t*)&g_aolo[o1] = packbf(v10 - __bfloat162float(hh1.x),
                                         v11 - __bfloat162float(hh1.y));
    }
}

// ---------------------------------------------------------------------------
extern "C" void kernel_launch(void* const* d_in, const int* in_sizes, int n_in,
                              void* d_out, int out_size)
{
    const float* x    = (const float*)d_in[0];
    const float* rc   = (const float*)d_in[1];
    const float* rs   = (const float*)d_in[2];
    const float* wqkv = (const float*)d_in[3];
    const float* wo   = (const float*)d_in[4];
    const int*   mask = (const int*)d_in[5];
    float* out = (float*)d_out;

    float *qkv_p;
    __nv_bfloat16 *xhi, *xlo, *aohi, *aolo, *wqTh, *wqTl, *woTh, *woTl;
    cudaGetSymbolAddress((void**)&qkv_p, g_qkv);
    cudaGetSymbolAddress((void**)&xhi, g_xhi);
    cudaGetSymbolAddress((void**)&xlo, g_xlo);
    cudaGetSymbolAddress((void**)&aohi, g_aohi);
    cudaGetSymbolAddress((void**)&aolo, g_aolo);
    cudaGetSymbolAddress((void**)&wqTh, g_wqTh);
    cudaGetSymbolAddress((void**)&wqTl, g_wqTl);
    cudaGetSymbolAddress((void**)&woTh, g_woTh);
    cudaGetSymbolAddress((void**)&woTl, g_woTl);

    const int GSM = 2 * (int)STAGEB;    // 81920
    cudaFuncSetAttribute((const void*)gemm_mma,
                         cudaFuncAttributeMaxDynamicSharedMemorySize, GSM);
    cudaFuncSetAttribute((const void*)flash_mma,
                         cudaFuncAttributeMaxDynamicSharedMemorySize, (int)FSMEM);

    dim3 blk(256);

    // 0) splits
    split_hilo<<<(NT * Dd / 4) / 256, blk>>>(x, xhi, xlo);
    splitT<<<dim3(3 * Dd / 32, Dd / 32), dim3(32, 8)>>>(wqkv, wqTh, wqTl, Dd, 3 * Dd);
    splitT<<<dim3(Dd / 32, Dd / 32), dim3(32, 8)>>>(wo, woTh, woTl, Dd, Dd);

    // 1) QKV projection (HMMA)
    gemm_mma<<<dim3(3 * Dd / 128, NT / 128), blk, GSM>>>(xhi, xlo, wqTh, wqTl,
                                                         qkv_p, NT, 3 * Dd, Dd);

    // 2) RoPE -> head-major bf16 hi/lo
    rope_kernel<<<(NT * Hh * 32) / 256, blk>>>(rc, rs);

    // 3) Flash attention (HMMA)
    flash_mma<<<dim3(Ll / 128, Hh, Bb), blk, FSMEM>>>(mask);

    // 4) Output projection (HMMA)
    gemm_mma<<<dim3(Dd / 128, NT / 128), blk, GSM>>>(aohi, aolo, woTh, woTl,
                                                     out, NT, Dd, Dd);
}